// round 6
// baseline (speedup 1.0000x reference)
#include <cuda_runtime.h>
#include <cuda_fp16.h>

// DenseMRConv: out[i] = concat(x[i], max_k(x[e[i,k]] - x[i])) @ W + b
// Two kernels: (1) convert x -> fp16 shadow (halves gather bytes),
// (2) fused gather/max/GEMM. Lane owns dims {2l,2l+1} and out cols {2l,2l+1}.

#define WPB 8
#define THREADS (WPB * 32)
#define D 64
#define KNBR 32
#define DIN 128
#define MB 8
#define MAXN 100000

__device__ __half2 g_xh[MAXN * (D / 2)];   // 12.8 MB fp16 shadow of x

// dynamic smem: Wp[32][2][32] float4 (32KB) then hs4[WPB*MB][32] float4 (32KB)
#define WP_F4   2048
#define HS_F4   (WPB * MB * 32)
#define SMEM_BYTES ((WP_F4 + HS_F4) * 16)

__global__ void __launch_bounds__(256) convert_kernel(const float2* __restrict__ x2, int n2) {
    const int e = blockIdx.x * 256 + threadIdx.x;
    if (e < n2) {
        const float2 v = x2[e];
        g_xh[e] = __floats2half2_rn(v.x, v.y);
    }
}

__global__ void __launch_bounds__(THREADS, 3) mrconv_kernel(
    const float* __restrict__ x,
    const int* __restrict__ edge_index,
    const float* __restrict__ W,
    const float* __restrict__ b,
    float* __restrict__ out,
    int N)
{
    extern __shared__ float4 sm[];
    float4* __restrict__ Wp  = sm;            // [d4][half][lane]
    float4* __restrict__ hs4 = sm + WP_F4;    // [(warp*MB+m)][d4]

    const int tid  = threadIdx.x;
    const int warp = tid >> 5;
    const int lane = tid & 31;

    // Stage permuted W: Wp[d4][h][l] = {W[db][2l],W[db][2l+1],W[db+1][2l],W[db+1][2l+1]},
    // db = 4*d4 + 2*h. One-time, coalesced float2 global reads.
    {
        const float2* W2 = (const float2*)W;
        for (int e = tid; e < WP_F4; e += THREADS) {
            const int l  = e & 31;
            const int h  = (e >> 5) & 1;
            const int d4 = e >> 6;
            const int db = 4 * d4 + 2 * h;
            const float2 a0 = W2[db * 32 + l];
            const float2 a1 = W2[(db + 1) * 32 + l];
            Wp[e] = make_float4(a0.x, a0.y, a1.x, a1.y);
        }
    }
    __syncthreads();

    const float b0 = b[2 * lane];
    const float b1 = b[2 * lane + 1];

    const float2* __restrict__ x2 = (const float2*)x;
    float2* __restrict__ out2     = (float2*)out;
    float2* __restrict__ hs2      = (float2*)hs4;

    const int gwarp  = blockIdx.x * WPB + warp;
    const int nwarps = gridDim.x * WPB;

    for (int i0 = gwarp * MB; i0 < N; i0 += nwarps * MB) {
        float2 xi[MB], dm[MB];
        int myidx[MB];

        #pragma unroll
        for (int m = 0; m < MB; m++) {
            const int i = min(i0 + m, N - 1);
            xi[m]    = x2[i * (D / 2) + lane];
            myidx[m] = edge_index[i * KNBR + lane];
            dm[m]    = make_float2(-INFINITY, -INFINITY);
        }

        // Gather from fp16 shadow: 1 coalesced 128B line per neighbor row
        #pragma unroll
        for (int m = 0; m < MB; m++) {
            #pragma unroll 16
            for (int k = 0; k < KNBR; k++) {
                const int j = __shfl_sync(0xffffffffu, myidx[m], k);
                const __half2 hj = __ldcg(&g_xh[j * (D / 2) + lane]);
                const float2 xj = __half22float2(hj);
                dm[m].x = fmaxf(dm[m].x, xj.x - xi[m].x);
                dm[m].y = fmaxf(dm[m].y, xj.y - xi[m].y);
            }
        }

        // Stage h = [x (slots 0..31), diff_max (slots 32..63)] per node
        #pragma unroll
        for (int m = 0; m < MB; m++) {
            const int base = (warp * MB + m) * 64;
            hs2[base + lane]      = xi[m];
            hs2[base + 32 + lane] = dm[m];
        }
        __syncwarp();

        float2 acc[MB];
        #pragma unroll
        for (int m = 0; m < MB; m++) acc[m] = make_float2(b0, b1);

        #pragma unroll 4
        for (int d4 = 0; d4 < 32; d4++) {
            const float4 wA = Wp[d4 * 64 + lane];
            const float4 wB = Wp[d4 * 64 + 32 + lane];
            #pragma unroll
            for (int m = 0; m < MB; m++) {
                const float4 h = hs4[(warp * MB + m) * 32 + d4]; // uniform broadcast
                acc[m].x = fmaf(h.x, wA.x, acc[m].x);
                acc[m].y = fmaf(h.x, wA.y, acc[m].y);
                acc[m].x = fmaf(h.y, wA.z, acc[m].x);
                acc[m].y = fmaf(h.y, wA.w, acc[m].y);
                acc[m].x = fmaf(h.z, wB.x, acc[m].x);
                acc[m].y = fmaf(h.z, wB.y, acc[m].y);
                acc[m].x = fmaf(h.w, wB.z, acc[m].x);
                acc[m].y = fmaf(h.w, wB.w, acc[m].y);
            }
        }

        #pragma unroll
        for (int m = 0; m < MB; m++)
            if (i0 + m < N) out2[(i0 + m) * (D / 2) + lane] = acc[m];
        __syncwarp();  // protect hs before next batch overwrites it
    }
}

extern "C" void kernel_launch(void* const* d_in, const int* in_sizes, int n_in,
                              void* d_out, int out_size) {
    const float* x  = (const float*)d_in[0];
    const int*   ei = (const int*)d_in[1];
    const float* W  = (const float*)d_in[2];
    const float* b  = (const float*)d_in[3];
    float* out = (float*)d_out;

    const int N = in_sizes[0] / D;
    const int n2 = N * (D / 2);

    static int smem_set = 0;
    if (!smem_set) {
        cudaFuncSetAttribute(mrconv_kernel,
                             cudaFuncAttributeMaxDynamicSharedMemorySize, SMEM_BYTES);
        smem_set = 1;
    }

    convert_kernel<<<(n2 + 255) / 256, 256>>>((const float2*)x, n2);

    // 64 KB smem/block -> 3 blocks/SM, 152 SMs
    const int grid = 456;
    mrconv_kernel<<<grid, THREADS, SMEM_BYTES>>>(x, ei, W, b, out, N);
}

// round 8
// speedup vs baseline: 1.1330x; 1.1330x over previous
#include <cuda_runtime.h>
#include <cuda_fp16.h>
#include <cstdint>

// DenseMRConv: out[i] = concat(x[i], max_k(x[e[i,k]] - x[i])) @ W + b
// k1: x -> fp16 shadow. k2: gather/max in half2 + fp32 FFMA GEMM epilogue.
// Lane owns dims {2l,2l+1} and output cols {2l,2l+1}. MB=8 nodes per warp.

#define WPB 8
#define THREADS (WPB * 32)
#define D 64
#define KNBR 32
#define MB 8
#define MAXN 100000

__device__ __half2 g_xh[MAXN * (D / 2)];   // 12.8 MB fp16 shadow of x

// smem: Wp 32KB | hs_x 16KB | hs_d 8KB (also used as idx stash pre-staging)
#define WP_F4   2048
#define HSX_F2  (WPB * MB * 32)            // float2 slots
#define HSD_U32 (WPB * MB * 32)            // half2 slots
#define SMEM_BYTES (WP_F4 * 16 + HSX_F2 * 8 + HSD_U32 * 4)

__global__ void __launch_bounds__(256) convert_kernel(const float2* __restrict__ x2, int n2) {
    const int e = blockIdx.x * 256 + threadIdx.x;
    if (e < n2) {
        const float2 v = x2[e];
        g_xh[e] = __floats2half2_rn(v.x, v.y);
    }
}

__global__ void __launch_bounds__(THREADS, 4) mrconv_kernel(
    const float* __restrict__ x,
    const int* __restrict__ edge_index,
    const float* __restrict__ W,
    const float* __restrict__ b,
    float* __restrict__ out,
    int N)
{
    extern __shared__ float4 sm[];
    float4*   __restrict__ Wp  = sm;                        // [d4][half][lane]
    float2*   __restrict__ hsx = (float2*)(sm + WP_F4);     // [(warp*MB+m)*32 + slot]
    uint32_t* __restrict__ hsd = (uint32_t*)((char*)(sm + WP_F4) + HSX_F2 * 8);

    const int tid  = threadIdx.x;
    const int warp = tid >> 5;
    const int lane = tid & 31;

    // Stage permuted W: Wp[d4][h][l] covers dims {4d4+2h, 4d4+2h+1} cols {2l,2l+1}
    {
        const float2* W2 = (const float2*)W;
        for (int e = tid; e < WP_F4; e += THREADS) {
            const int l  = e & 31;
            const int h  = (e >> 5) & 1;
            const int d4 = e >> 6;
            const int db = 4 * d4 + 2 * h;
            const float2 a0 = W2[db * 32 + l];
            const float2 a1 = W2[(db + 1) * 32 + l];
            Wp[e] = make_float4(a0.x, a0.y, a1.x, a1.y);
        }
    }
    __syncthreads();

    const float b0 = b[2 * lane];
    const float b1 = b[2 * lane + 1];

    const float2* __restrict__ x2 = (const float2*)x;
    float2* __restrict__ out2     = (float2*)out;

    // per-warp views
    float2*   hx = hsx + warp * MB * 32;    // [m*32 + slot]
    uint32_t* hd = hsd + warp * MB * 32;    // [m*32 + slot]; pre-staging: idx stash

    const int gwarp  = blockIdx.x * WPB + warp;
    const int nwarps = gridDim.x * WPB;

    for (int i0 = gwarp * MB; i0 < N; i0 += nwarps * MB) {
        float2  xi[MB];
        __half2 xih[MB], dmh[MB];

        #pragma unroll
        for (int m = 0; m < MB; m++) {
            const int i = min(i0 + m, N - 1);
            xi[m]  = x2[i * (D / 2) + lane];
            xih[m] = __floats2half2_rn(xi[m].x, xi[m].y);
            hd[m * 32 + lane] = (uint32_t)edge_index[i * KNBR + lane]; // idx stash
            dmh[m] = __floats2half2_rn(-INFINITY, -INFINITY);
        }
        __syncwarp();

        // Gather from fp16 shadow; diff+max in half2 (4 instr / neighbor)
        #pragma unroll
        for (int m = 0; m < MB; m++) {
            #pragma unroll 16
            for (int k = 0; k < KNBR; k++) {
                const int j = (int)hd[m * 32 + k];             // uniform LDS broadcast
                const __half2 xj = __ldcg(&g_xh[j * (D / 2) + lane]);
                dmh[m] = __hmax2(dmh[m], __hsub2(xj, xih[m]));
            }
        }
        __syncwarp();   // idx region about to be overwritten with dm

        #pragma unroll
        for (int m = 0; m < MB; m++) {
            hx[m * 32 + lane] = xi[m];                          // dims 2l,2l+1 (fp32)
            hd[m * 32 + lane] = *(const uint32_t*)&dmh[m];      // dims 2l,2l+1 (half2)
        }
        __syncwarp();

        float2 acc[MB];
        #pragma unroll
        for (int m = 0; m < MB; m++) acc[m] = make_float2(b0, b1);

        const float4* hx4 = (const float4*)hx;                  // [m*16 + t]
        const uint2*  hd2 = (const uint2*)hd;                   // [m*16 + t]

        #pragma unroll 4
        for (int t = 0; t < 16; t++) {
            // x part: dims 4t..4t+3  -> Wp rows t
            const float4 wA = Wp[t * 64 + lane];
            const float4 wB = Wp[t * 64 + 32 + lane];
            // dm part: dims 64+4t..64+4t+3 -> Wp rows 16+t
            const float4 wC = Wp[(16 + t) * 64 + lane];
            const float4 wD = Wp[(16 + t) * 64 + 32 + lane];
            #pragma unroll
            for (int m = 0; m < MB; m++) {
                const float4 h = hx4[m * 16 + t];               // uniform broadcast
                acc[m].x = fmaf(h.x, wA.x, acc[m].x);
                acc[m].y = fmaf(h.x, wA.y, acc[m].y);
                acc[m].x = fmaf(h.y, wA.z, acc[m].x);
                acc[m].y = fmaf(h.y, wA.w, acc[m].y);
                acc[m].x = fmaf(h.z, wB.x, acc[m].x);
                acc[m].y = fmaf(h.z, wB.y, acc[m].y);
                acc[m].x = fmaf(h.w, wB.z, acc[m].x);
                acc[m].y = fmaf(h.w, wB.w, acc[m].y);

                const uint2 dp = hd2[m * 16 + t];               // uniform broadcast
                const float2 g0 = __half22float2(*(const __half2*)&dp.x);
                const float2 g1 = __half22float2(*(const __half2*)&dp.y);
                acc[m].x = fmaf(g0.x, wC.x, acc[m].x);
                acc[m].y = fmaf(g0.x, wC.y, acc[m].y);
                acc[m].x = fmaf(g0.y, wC.z, acc[m].x);
                acc[m].y = fmaf(g0.y, wC.w, acc[m].y);
                acc[m].x = fmaf(g1.x, wD.x, acc[m].x);
                acc[m].y = fmaf(g1.x, wD.y, acc[m].y);
                acc[m].x = fmaf(g1.y, wD.z, acc[m].x);
                acc[m].y = fmaf(g1.y, wD.w, acc[m].y);
            }
        }

        #pragma unroll
        for (int m = 0; m < MB; m++)
            if (i0 + m < N) out2[(i0 + m) * (D / 2) + lane] = acc[m];
        __syncwarp();   // protect hs before next batch
    }
}

extern "C" void kernel_launch(void* const* d_in, const int* in_sizes, int n_in,
                              void* d_out, int out_size) {
    const float* x  = (const float*)d_in[0];
    const int*   ei = (const int*)d_in[1];
    const float* W  = (const float*)d_in[2];
    const float* b  = (const float*)d_in[3];
    float* out = (float*)d_out;

    const int N = in_sizes[0] / D;
    const int n2 = N * (D / 2);

    static int smem_set = 0;
    if (!smem_set) {
        cudaFuncSetAttribute(mrconv_kernel,
                             cudaFuncAttributeMaxDynamicSharedMemorySize, SMEM_BYTES);
        smem_set = 1;
    }

    convert_kernel<<<(n2 + 255) / 256, 256>>>((const float2*)x, n2);

    // 56 KB smem, <=64 regs -> 4 blocks/SM, 152 SMs
    const int grid = 608;
    mrconv_kernel<<<grid, THREADS, SMEM_BYTES>>>(x, ei, W, b, out, N);
}

// round 9
// speedup vs baseline: 1.2278x; 1.0837x over previous
#include <cuda_runtime.h>
#include <cuda_fp16.h>
#include <cstdint>

// DenseMRConv: out = x @ (Wt - Wb) + (max_k x_j) @ Wb + b
//   (identical math: concat(x, max(x_j) - x) @ [Wt; Wb] + b)
// k1: x -> fp16 shadow. k2: gather/hmax2 + packed f32x2 GEMM epilogue,
// two nodes per FMA. Lane owns dims {2l,2l+1} and output cols {2l,2l+1}.

#define WPB 8
#define THREADS (WPB * 32)
#define D 64
#define KNBR 32
#define MB 8
#define MAXN 100000

__device__ __half2 g_xh[MAXN * (D / 2)];   // 12.8 MB fp16 shadow of x

// smem: Wp 32KB | hp 2KB/warp (idx stash -> x-pairs -> mx-pairs)
#define WP_F4 2048
#define SMEM_BYTES (WP_F4 * 16 + WPB * 2048)

__global__ void __launch_bounds__(256) convert_kernel(const float2* __restrict__ x2, int n2) {
    const int e = blockIdx.x * 256 + threadIdx.x;
    if (e < n2) {
        const float2 v = x2[e];
        g_xh[e] = __floats2half2_rn(v.x, v.y);
    }
}

__device__ __forceinline__ void fma2(unsigned long long& d,
                                     unsigned long long a, unsigned long long b) {
    asm("fma.rn.f32x2 %0, %1, %2, %0;" : "+l"(d) : "l"(a), "l"(b));
}
__device__ __forceinline__ unsigned long long pack2(float v) {
    unsigned long long r;
    asm("mov.b64 %0, {%1, %1};" : "=l"(r) : "f"(v));
    return r;
}
__device__ __forceinline__ float2 unpack2(unsigned long long v) {
    float2 r;
    asm("mov.b64 {%0, %1}, %2;" : "=f"(r.x), "=f"(r.y) : "l"(v));
    return r;
}

// One 2-dim group: w = {w[d][c0], w[d][c1], w[d+1][c0], w[d+1][c1]}, dl = local dim
__device__ __forceinline__ void epi_group(const float4 w, const ulonglong2* __restrict__ u2,
                                          int dl, unsigned long long acc[4][2]) {
    const unsigned long long a00 = pack2(w.x), a01 = pack2(w.y);
    const unsigned long long a10 = pack2(w.z), a11 = pack2(w.w);
    const ulonglong2 hA = u2[dl * 2];         // dim dl,   pairs 0,1
    const ulonglong2 hB = u2[dl * 2 + 1];     // dim dl,   pairs 2,3
    const ulonglong2 hC = u2[dl * 2 + 2];     // dim dl+1, pairs 0,1
    const ulonglong2 hD = u2[dl * 2 + 3];     // dim dl+1, pairs 2,3
    fma2(acc[0][0], hA.x, a00); fma2(acc[0][1], hA.x, a01);
    fma2(acc[1][0], hA.y, a00); fma2(acc[1][1], hA.y, a01);
    fma2(acc[2][0], hB.x, a00); fma2(acc[2][1], hB.x, a01);
    fma2(acc[3][0], hB.y, a00); fma2(acc[3][1], hB.y, a01);
    fma2(acc[0][0], hC.x, a10); fma2(acc[0][1], hC.x, a11);
    fma2(acc[1][0], hC.y, a10); fma2(acc[1][1], hC.y, a11);
    fma2(acc[2][0], hD.x, a10); fma2(acc[2][1], hD.x, a11);
    fma2(acc[3][0], hD.y, a10); fma2(acc[3][1], hD.y, a11);
}

__device__ __forceinline__ void epi_pass(const float4* __restrict__ Wp, int t0,
                                         const ulonglong2* __restrict__ u2, int lane,
                                         unsigned long long acc[4][2]) {
    #pragma unroll 2
    for (int t = 0; t < 16; t++) {
        const float4 wA = Wp[(t0 + t) * 64 + lane];        // local dims 4t, 4t+1
        const float4 wB = Wp[(t0 + t) * 64 + 32 + lane];   // local dims 4t+2, 4t+3
        epi_group(wA, u2, 4 * t, acc);
        epi_group(wB, u2, 4 * t + 2, acc);
    }
}

__global__ void __launch_bounds__(THREADS, 4) mrconv_kernel(
    const float* __restrict__ x,
    const int* __restrict__ edge_index,
    const float* __restrict__ W,
    const float* __restrict__ b,
    float* __restrict__ out,
    int N)
{
    extern __shared__ float4 sm[];
    float4* __restrict__ Wp = sm;                       // W' permuted, 32 KB
    char* hpb = (char*)(sm + WP_F4);                    // 2 KB per warp

    const int tid  = threadIdx.x;
    const int warp = tid >> 5;
    const int lane = tid & 31;

    // Stage W' : rows 0..63 = Wt - Wb, rows 64..127 = Wb.
    // Wp[t][h][l] = {W'[db][2l], W'[db][2l+1], W'[db+1][2l], W'[db+1][2l+1]}, db=4t+2h
    {
        const float2* W2 = (const float2*)W;
        for (int e = tid; e < WP_F4; e += THREADS) {
            const int l  = e & 31;
            const int h  = (e >> 5) & 1;
            const int t  = e >> 6;
            const int db = 4 * t + 2 * h;
            float2 a0 = W2[db * 32 + l];
            float2 a1 = W2[(db + 1) * 32 + l];
            if (db < 64) {
                const float2 s0 = W2[(db + 64) * 32 + l];
                const float2 s1 = W2[(db + 65) * 32 + l];
                a0.x -= s0.x; a0.y -= s0.y;
                a1.x -= s1.x; a1.y -= s1.y;
            }
            Wp[e] = make_float4(a0.x, a0.y, a1.x, a1.y);
        }
    }
    __syncthreads();

    const unsigned long long bb0 = pack2(b[2 * lane]);
    const unsigned long long bb1 = pack2(b[2 * lane + 1]);

    const float2* __restrict__ x2 = (const float2*)x;
    float2* __restrict__ out2     = (float2*)out;

    // per-warp staging region (reused: idx -> x-pairs -> mx-pairs)
    char* hp = hpb + warp * 2048;
    int*              ids = (int*)hp;
    float4*           f4  = (float4*)hp;
    const ulonglong2* u2  = (const ulonglong2*)hp;

    const int gwarp  = blockIdx.x * WPB + warp;
    const int nwarps = gridDim.x * WPB;

    const __half2 hneg = __floats2half2_rn(-INFINITY, -INFINITY);

    for (int i0 = gwarp * MB; i0 < N; i0 += nwarps * MB) {
        float2  xi[MB];
        __half2 mxh[MB];

        #pragma unroll
        for (int m = 0; m < MB; m++) {
            const int i = min(i0 + m, N - 1);
            xi[m] = x2[i * (D / 2) + lane];
            ids[m * 32 + lane] = edge_index[i * KNBR + lane];
            mxh[m] = hneg;
        }
        __syncwarp();

        // Gather: mx = max_k x_j (fp16); idx read 4-at-a-time (uniform LDS.128)
        #pragma unroll
        for (int m = 0; m < MB; m++) {
            const int4* ip = (const int4*)(ids + m * 32);
            #pragma unroll 4
            for (int k4 = 0; k4 < 8; k4++) {
                const int4 jj = ip[k4];
                mxh[m] = __hmax2(mxh[m], __ldcg(&g_xh[jj.x * (D / 2) + lane]));
                mxh[m] = __hmax2(mxh[m], __ldcg(&g_xh[jj.y * (D / 2) + lane]));
                mxh[m] = __hmax2(mxh[m], __ldcg(&g_xh[jj.z * (D / 2) + lane]));
                mxh[m] = __hmax2(mxh[m], __ldcg(&g_xh[jj.w * (D / 2) + lane]));
            }
        }
        __syncwarp();   // idx region about to be overwritten

        unsigned long long acc[4][2];
        #pragma unroll
        for (int p = 0; p < 4; p++) { acc[p][0] = bb0; acc[p][1] = bb1; }

        // Pass 0: h = x, W' rows 0..63. Stage x as node-pairs.
        f4[lane * 4 + 0] = make_float4(xi[0].x, xi[1].x, xi[2].x, xi[3].x);
        f4[lane * 4 + 1] = make_float4(xi[4].x, xi[5].x, xi[6].x, xi[7].x);
        f4[lane * 4 + 2] = make_float4(xi[0].y, xi[1].y, xi[2].y, xi[3].y);
        f4[lane * 4 + 3] = make_float4(xi[4].y, xi[5].y, xi[6].y, xi[7].y);
        __syncwarp();
        epi_pass(Wp, 0, u2, lane, acc);
        __syncwarp();

        // Pass 1: h = mx (fp32), W' rows 64..127
        {
            float2 mx[MB];
            #pragma unroll
            for (int m = 0; m < MB; m++) mx[m] = __half22float2(mxh[m]);
            f4[lane * 4 + 0] = make_float4(mx[0].x, mx[1].x, mx[2].x, mx[3].x);
            f4[lane * 4 + 1] = make_float4(mx[4].x, mx[5].x, mx[6].x, mx[7].x);
            f4[lane * 4 + 2] = make_float4(mx[0].y, mx[1].y, mx[2].y, mx[3].y);
            f4[lane * 4 + 3] = make_float4(mx[4].y, mx[5].y, mx[6].y, mx[7].y);
        }
        __syncwarp();
        epi_pass(Wp, 16, u2, lane, acc);

        // Store: acc[p][c] = {out[2p][c], out[2p+1][c]}
        #pragma unroll
        for (int p = 0; p < 4; p++) {
            const float2 c0 = unpack2(acc[p][0]);
            const float2 c1 = unpack2(acc[p][1]);
            const int iA = i0 + 2 * p, iB = iA + 1;
            if (iA < N) out2[iA * (D / 2) + lane] = make_float2(c0.x, c1.x);
            if (iB < N) out2[iB * (D / 2) + lane] = make_float2(c0.y, c1.y);
        }
        __syncwarp();   // protect hp before next batch's idx stash
    }
}

extern "C" void kernel_launch(void* const* d_in, const int* in_sizes, int n_in,
                              void* d_out, int out_size) {
    const float* x  = (const float*)d_in[0];
    const int*   ei = (const int*)d_in[1];
    const float* W  = (const float*)d_in[2];
    const float* b  = (const float*)d_in[3];
    float* out = (float*)d_out;

    const int N = in_sizes[0] / D;
    const int n2 = N * (D / 2);

    static int smem_set = 0;
    if (!smem_set) {
        cudaFuncSetAttribute(mrconv_kernel,
                             cudaFuncAttributeMaxDynamicSharedMemorySize, SMEM_BYTES);
        smem_set = 1;
    }

    convert_kernel<<<(n2 + 255) / 256, 256>>>((const float2*)x, n2);

    // 48 KB smem, <=64 regs -> 4 blocks/SM, 152 SMs
    const int grid = 608;
    mrconv_kernel<<<grid, THREADS, SMEM_BYTES>>>(x, ei, W, b, out, N);
}